// round 9
// baseline (speedup 1.0000x reference)
#include <cuda_runtime.h>
#include <cstdint>

#define N_   16
#define C_   384
#define S_   1024
#define NH_  6
#define D_   64
#define C3_  1152
#define M_   (N_*S_)

// hi/lo interleaved layouts: element i holds {hi,lo} at [2i, 2i+1]
__device__ float g_tok_hl[M_*C_*2];
__device__ float g_wqkv_hl[C3_*C_*2];
__device__ float g_wout_hl[C_*C_*2];
__device__ float g_q[N_*NH_*S_*D_];                 // fp32, 0.125 folded
__device__ float g_khl[N_*NH_*S_*D_*2];             // [nh][s][d]{h,l}
__device__ float g_vhl[N_*NH_*D_*S_*2];             // V^T [nh][d][s]{h,l}
__device__ float g_ao_hl[M_*C_*2];

__device__ __forceinline__ float tf32_rna(float x) {
    uint32_t r; asm("cvt.rna.tf32.f32 %0, %1;" : "=r"(r) : "f"(x));
    return __uint_as_float(r);
}
__device__ __forceinline__ uint32_t smem_u32(const void* p) {
    uint32_t a;
    asm("{ .reg .u64 t; cvta.to.shared.u64 t, %1; cvt.u32.u64 %0, t; }" : "=r"(a) : "l"(p));
    return a;
}
__device__ __forceinline__ void lds64(uint32_t a, uint32_t& x, uint32_t& y) {
    asm volatile("ld.shared.v2.b32 {%0,%1}, [%2];" : "=r"(x), "=r"(y) : "r"(a));
}
__device__ __forceinline__ void cp16(uint32_t saddr, const float* g) {
    size_t ga = __cvta_generic_to_global((const void*)g);
    asm volatile("cp.async.cg.shared.global [%0], [%1], 16;" :: "r"(saddr), "l"(ga) : "memory");
}
#define CP_COMMIT() asm volatile("cp.async.commit_group;" ::: "memory")
#define CP_WAIT0()  asm volatile("cp.async.wait_group 0;" ::: "memory")
#define CP_WAIT1()  asm volatile("cp.async.wait_group 1;" ::: "memory")
#define CP_WAIT2()  asm volatile("cp.async.wait_group 2;" ::: "memory")
#define FU(x) __float_as_uint(x)

#define MMA_TF32(d, a, b0, b1)                                              \
    asm volatile("mma.sync.aligned.m16n8k8.row.col.f32.tf32.tf32.f32 "      \
        "{%0,%1,%2,%3}, {%4,%5,%6,%7}, {%8,%9}, {%0,%1,%2,%3};"             \
        : "+f"((d)[0]), "+f"((d)[1]), "+f"((d)[2]), "+f"((d)[3])            \
        : "r"((a)[0]), "r"((a)[1]), "r"((a)[2]), "r"((a)[3]),               \
          "r"(b0), "r"(b1))

// ---------------- input prep ----------------
__global__ void transpose_x(const float* __restrict__ x) {
    __shared__ float t[32][33];
    int n = blockIdx.z, k0 = blockIdx.y * 32, s0 = blockIdx.x * 32;
    int tx = threadIdx.x, ty = threadIdx.y;
    const float* src = x + ((size_t)n * C_ + k0) * S_ + s0;
    #pragma unroll
    for (int j = 0; j < 4; j++)
        t[ty + 8 * j][tx] = src[(size_t)(ty + 8 * j) * S_ + tx];
    __syncthreads();
    size_t base = ((size_t)n * S_ + s0) * C_ + k0;
    #pragma unroll
    for (int j = 0; j < 4; j++) {
        float a = t[tx][ty + 8 * j];
        float h = tf32_rna(a);
        size_t o = base + (size_t)(ty + 8 * j) * C_ + tx;
        *(float2*)(g_tok_hl + o * 2) = make_float2(h, tf32_rna(a - h));
    }
}
__global__ void split_wqkv(const float* __restrict__ w) {
    int i = blockIdx.x * 256 + threadIdx.x;
    if (i < C3_ * C_) {
        float a = w[i], h = tf32_rna(a);
        *(float2*)(g_wqkv_hl + (size_t)i * 2) = make_float2(h, tf32_rna(a - h));
    }
}
__global__ void split_wout(const float* __restrict__ w) {
    int i = blockIdx.x * 256 + threadIdx.x;
    if (i < C_ * C_) {
        float a = w[i], h = tf32_rna(a);
        *(float2*)(g_wout_hl + (size_t)i * 2) = make_float2(h, tf32_rna(a - h));
    }
}

// ---------------- 3xTF32 mma.sync GEMM, hi/lo interleaved ----------------
// smem row stride 40 floats (≡8 mod 32 -> LDS.64 conflict-free)
#define GSTR 40
#define ARR_B (128*GSTR*4)     // 20480 bytes per array
#define STAGE_B (2*ARR_B)      // A + B
#define GEMM_SMEM (2*STAGE_B)  // 81920

__global__ __launch_bounds__(256) void mma_gemm(
    int mode, const float* __restrict__ bias, float* __restrict__ out)
{
    extern __shared__ __align__(16) char smem[];
    uint32_t sbase = smem_u32(smem);
    int tid = threadIdx.x;
    int lane = tid & 31, w = tid >> 5;
    int wm = w & 3, wn = w >> 2;
    int by = blockIdx.y, bx = blockIdx.x;

    const float *Ahl, *Bhl;
    if (mode == 0) { Ahl = g_tok_hl  + (size_t)by * 128 * C_ * 2;
                     Bhl = g_wqkv_hl + (size_t)bx * 128 * C_ * 2; }
    else           { Ahl = g_wout_hl + (size_t)by * 128 * C_ * 2;
                     Bhl = g_ao_hl   + (size_t)bx * 128 * C_ * 2; }

    float acc[2][8][4];
    #pragma unroll
    for (int i = 0; i < 2; i++)
        #pragma unroll
        for (int j = 0; j < 8; j++)
            #pragma unroll
            for (int q = 0; q < 4; q++) acc[i][j][q] = 0.0f;

    auto issue = [&](int c, int st) {
        uint32_t s0 = sbase + st * STAGE_B;
        #pragma unroll
        for (int i = 0; i < 4; i++) {
            int idx = i * 256 + tid;          // 0..1023
            int row = idx >> 3, seg = idx & 7;  // 8 segs x 4 floats = 32 floats/row
            size_t go = ((size_t)row * C_ + c * 16) * 2 + seg * 4;
            uint32_t so = row * (GSTR * 4) + seg * 16;
            cp16(s0 + so,         Ahl + go);
            cp16(s0 + ARR_B + so, Bhl + go);
        }
        CP_COMMIT();
    };

    issue(0, 0);
    const int NCH = C_ / 16;
    for (int c = 0; c < NCH; c++) {
        int st = c & 1;
        if (c + 1 < NCH) { issue(c + 1, st ^ 1); CP_WAIT1(); }
        else             { CP_WAIT0(); }
        __syncthreads();

        uint32_t sA = sbase + st * STAGE_B;
        uint32_t sB = sA + ARR_B;

        #pragma unroll
        for (int sub = 0; sub < 2; sub++) {
            int kb = sub * 8 + (lane & 3);
            uint32_t ahi[2][4], alo[2][4];
            #pragma unroll
            for (int mi = 0; mi < 2; mi++) {
                int r0 = wm * 32 + mi * 16 + (lane >> 2);
                uint32_t o0 = (uint32_t)r0 * (GSTR * 4) + (uint32_t)kb * 8;
                uint32_t o1 = o0 + 8 * (GSTR * 4);
                lds64(sA + o0,      ahi[mi][0], alo[mi][0]);
                lds64(sA + o1,      ahi[mi][1], alo[mi][1]);
                lds64(sA + o0 + 32, ahi[mi][2], alo[mi][2]);
                lds64(sA + o1 + 32, ahi[mi][3], alo[mi][3]);
            }
            #pragma unroll
            for (int ni = 0; ni < 8; ni++) {
                int n0 = wn * 64 + ni * 8 + (lane >> 2);
                uint32_t bo = (uint32_t)n0 * (GSTR * 4) + (uint32_t)kb * 8;
                uint32_t bh0, bl0, bh1, bl1;
                lds64(sB + bo,      bh0, bl0);
                lds64(sB + bo + 32, bh1, bl1);
                #pragma unroll
                for (int mi = 0; mi < 2; mi++) {
                    MMA_TF32(acc[mi][ni], ahi[mi], bh0, bh1);
                    MMA_TF32(acc[mi][ni], ahi[mi], bl0, bl1);
                    MMA_TF32(acc[mi][ni], alo[mi], bh0, bh1);
                }
            }
        }
        __syncthreads();
    }

    int row = lane >> 2, colp = (lane & 3) * 2;
    if (mode == 0) {
        #pragma unroll
        for (int ni = 0; ni < 8; ni++) {
            int rf = bx * 128 + wn * 64 + ni * 8 + colp;
            int t = rf / C_;
            int rem = rf - t * C_;
            int h = rem >> 6, d = rem & 63;
            #pragma unroll
            for (int mi = 0; mi < 2; mi++) {
                int mb = by * 128 + wm * 32 + mi * 16 + row;
                #pragma unroll
                for (int rr = 0; rr < 2; rr++) {
                    int m = mb + rr * 8;
                    int n = m >> 10, s = m & 1023;
                    int nh = n * NH_ + h;
                    float v0 = acc[mi][ni][rr * 2], v1 = acc[mi][ni][rr * 2 + 1];
                    if (t == 0) {
                        *(float2*)(g_q + ((size_t)nh * S_ + s) * D_ + d) =
                            make_float2(v0 * 0.125f, v1 * 0.125f);
                    } else if (t == 1) {
                        float h0 = tf32_rna(v0), h1 = tf32_rna(v1);
                        size_t off = (((size_t)nh * S_ + s) * D_ + d) * 2;
                        *(float4*)(g_khl + off) =
                            make_float4(h0, tf32_rna(v0 - h0), h1, tf32_rna(v1 - h1));
                    } else {
                        float h0 = tf32_rna(v0), h1 = tf32_rna(v1);
                        size_t o0 = (((size_t)nh * D_ + d) * S_ + s) * 2;
                        size_t o1 = (((size_t)nh * D_ + d + 1) * S_ + s) * 2;
                        *(float2*)(g_vhl + o0) = make_float2(h0, tf32_rna(v0 - h0));
                        *(float2*)(g_vhl + o1) = make_float2(h1, tf32_rna(v1 - h1));
                    }
                }
            }
        }
    } else {
        #pragma unroll
        for (int ni = 0; ni < 8; ni++) {
            int m = bx * 128 + wn * 64 + ni * 8 + colp;
            int n = m >> 10, s = m & 1023;
            #pragma unroll
            for (int mi = 0; mi < 2; mi++) {
                int cb = by * 128 + wm * 32 + mi * 16 + row;
                #pragma unroll
                for (int rr = 0; rr < 2; rr++) {
                    int cc = cb + rr * 8;
                    float bb = bias[cc];
                    float2 v = make_float2(acc[mi][ni][rr * 2] + bb,
                                           acc[mi][ni][rr * 2 + 1] + bb);
                    *(float2*)(out + ((size_t)n * C_ + cc) * S_ + s) = v;
                }
            }
        }
    }
}

// ---------------- tensor-core flash attention (hi/lo interleaved K/V) ------
// 256 thr; warp w owns q rows [w*16, w*16+16). 64-key tiles, 16 iters.
// K/V tiles in smem with row stride 136 floats (≡8 mod 32, LDS.64 conflict-free).
#define AST 68
#define KVSTR 136
#define KVTILE (64*KVSTR)        // 8704 floats per interleaved tile
#define ATT2_SMEM ((8704 + 2*KVTILE + 2*KVTILE) * 4)   // Pb + Khl(2) + Vhl(2)

__global__ __launch_bounds__(256) void attn_mma() {
    extern __shared__ __align__(16) float sm[];
    float* Pb  = sm;                    // [128][68]: Q staging, then P
    float* Khl = sm + 8704;             // 2 x [64][136]
    float* Vhl = Khl + 2 * KVTILE;      // 2 x [64][136]  (V^T: [d][key])

    int tid = threadIdx.x;
    int lane = tid & 31, w = tid >> 5;
    int rq = lane >> 2, kq = lane & 3;
    int nh = blockIdx.y, q0 = blockIdx.x * 128;

    const float* qg   = g_q   + ((size_t)nh * S_ + q0) * D_;
    const float* khlg = g_khl + (size_t)nh * S_ * D_ * 2;
    const float* vhlg = g_vhl + (size_t)nh * D_ * S_ * 2;

    // group 1: Q -> Pb (2048 segs)
    #pragma unroll
    for (int i = 0; i < 8; i++) {
        int idx = i * 256 + tid;
        int r = idx >> 4, sg = idx & 15;
        cp16(smem_u32(&Pb[r * AST + sg * 4]), qg + (size_t)r * D_ + sg * 4);
    }
    CP_COMMIT();

    // groups 2,3: K/V tiles 0,1 (each tile: 64 rows x 32 segs = 2048 segs per array)
    #pragma unroll
    for (int t = 0; t < 2; t++) {
        #pragma unroll
        for (int i = 0; i < 8; i++) {
            int idx = i * 256 + tid;
            int row = idx >> 5, sg = idx & 31;
            uint32_t so = (uint32_t)(t * KVTILE + row * KVSTR) * 4 + sg * 16;
            cp16(smem_u32(Khl) + so, khlg + ((size_t)(t * 64 + row) * D_) * 2 + sg * 4);
            cp16(smem_u32(Vhl) + so, vhlg + ((size_t)row * S_ + t * 64) * 2 + sg * 4);
        }
        CP_COMMIT();
    }

    CP_WAIT2();
    __syncthreads();

    // Q fragments, hi/lo split in registers (exact)
    uint32_t qah[8][4], qal[8][4];
    {
        const float* q0p = &Pb[(w * 16 + rq) * AST + kq];
        #pragma unroll
        for (int s = 0; s < 8; s++) {
            float f[4];
            f[0] = q0p[s * 8];           f[1] = q0p[8 * AST + s * 8];
            f[2] = q0p[s * 8 + 4];       f[3] = q0p[8 * AST + s * 8 + 4];
            #pragma unroll
            for (int j = 0; j < 4; j++) {
                float h = tf32_rna(f[j]);
                qah[s][j] = FU(h);
                qal[s][j] = FU(tf32_rna(f[j] - h));
            }
        }
    }
    __syncthreads();

    float o[8][4];
    #pragma unroll
    for (int n = 0; n < 8; n++)
        #pragma unroll
        for (int j = 0; j < 4; j++) o[n][j] = 0.0f;
    float m0 = -1e30f, m1 = -1e30f, l0 = 0.0f, l1 = 0.0f;

    uint32_t kbase = smem_u32(Khl);
    uint32_t vbase = smem_u32(Vhl);

    for (int kt = 0; kt < 16; kt++) {
        if (kt < 15) { CP_WAIT1(); } else { CP_WAIT0(); }
        __syncthreads();
        uint32_t boff = (uint32_t)((kt & 1) * KVTILE) * 4;

        // ---- QK^T (3-pass, interleaved LDS.64) ----
        float acc[8][4];
        #pragma unroll
        for (int n = 0; n < 8; n++)
            #pragma unroll
            for (int j = 0; j < 4; j++) acc[n][j] = 0.0f;

        #pragma unroll
        for (int s = 0; s < 8; s++) {
            #pragma unroll
            for (int n = 0; n < 8; n++) {
                uint32_t bo = boff + (uint32_t)((n * 8 + rq) * KVSTR + (s * 8 + kq) * 2) * 4;
                uint32_t bh0, bl0, bh1, bl1;
                lds64(kbase + bo,      bh0, bl0);
                lds64(kbase + bo + 32, bh1, bl1);
                MMA_TF32(acc[n], qah[s], bh0, bh1);
                MMA_TF32(acc[n], qah[s], bl0, bl1);
                MMA_TF32(acc[n], qal[s], bh0, bh1);
            }
        }

        // ---- softmax (rows rq, rq+8 of this warp's 16) ----
        float t0 = -1e30f, t1 = -1e30f;
        #pragma unroll
        for (int n = 0; n < 8; n++) {
            t0 = fmaxf(t0, fmaxf(acc[n][0], acc[n][1]));
            t1 = fmaxf(t1, fmaxf(acc[n][2], acc[n][3]));
        }
        t0 = fmaxf(t0, __shfl_xor_sync(0xffffffffu, t0, 1));
        t0 = fmaxf(t0, __shfl_xor_sync(0xffffffffu, t0, 2));
        t1 = fmaxf(t1, __shfl_xor_sync(0xffffffffu, t1, 1));
        t1 = fmaxf(t1, __shfl_xor_sync(0xffffffffu, t1, 2));
        float mn0 = fmaxf(m0, t0), mn1 = fmaxf(m1, t1);
        float c0 = __expf(m0 - mn0), c1 = __expf(m1 - mn1);
        m0 = mn0; m1 = mn1;
        l0 *= c0; l1 *= c1;
        #pragma unroll
        for (int n = 0; n < 8; n++) {
            o[n][0] *= c0; o[n][1] *= c0; o[n][2] *= c1; o[n][3] *= c1;
        }

        float* pr = &Pb[(w * 16 + rq) * AST + kq * 2];
        #pragma unroll
        for (int n = 0; n < 8; n++) {
            float p0 = __expf(acc[n][0] - m0), p1 = __expf(acc[n][1] - m0);
            float p2 = __expf(acc[n][2] - m1), p3 = __expf(acc[n][3] - m1);
            l0 += p0 + p1; l1 += p2 + p3;
            *(float2*)(pr + n * 8)           = make_float2(p0, p1);
            *(float2*)(pr + 8 * AST + n * 8) = make_float2(p2, p3);
        }
        __syncwarp();

        // ---- PV (3-pass; P split in registers; V interleaved LDS.64) ----
        const float* pa = &Pb[(w * 16 + rq) * AST + kq];
        #pragma unroll
        for (int s = 0; s < 8; s++) {
            float f[4];
            f[0] = pa[s * 8];       f[1] = pa[8 * AST + s * 8];
            f[2] = pa[s * 8 + 4];   f[3] = pa[8 * AST + s * 8 + 4];
            uint32_t ph[4], pl[4];
            #pragma unroll
            for (int j = 0; j < 4; j++) {
                float h = tf32_rna(f[j]);
                ph[j] = FU(h);
                pl[j] = FU(tf32_rna(f[j] - h));
            }
            #pragma unroll
            for (int n = 0; n < 8; n++) {
                uint32_t bo = boff + (uint32_t)((n * 8 + rq) * KVSTR + (s * 8 + kq) * 2) * 4;
                uint32_t bh0, bl0, bh1, bl1;
                lds64(vbase + bo,      bh0, bl0);
                lds64(vbase + bo + 32, bh1, bl1);
                MMA_TF32(o[n], ph, bh0, bh1);
                MMA_TF32(o[n], ph, bl0, bl1);
                MMA_TF32(o[n], pl, bh0, bh1);
            }
        }
        __syncthreads();

        if (kt + 2 < 16) {
            int t = kt + 2;
            #pragma unroll
            for (int i = 0; i < 8; i++) {
                int idx = i * 256 + tid;
                int row = idx >> 5, sg = idx & 31;
                uint32_t so = boff + (uint32_t)(row * KVSTR) * 4 + sg * 16;
                cp16(smem_u32(Khl) + so, khlg + ((size_t)(t * 64 + row) * D_) * 2 + sg * 4);
                cp16(smem_u32(Vhl) + so, vhlg + ((size_t)row * S_ + t * 64) * 2 + sg * 4);
            }
            CP_COMMIT();
        }
    }

    // ---- epilogue: normalize + hi/lo split -> g_ao_hl ----
    l0 += __shfl_xor_sync(0xffffffffu, l0, 1);
    l0 += __shfl_xor_sync(0xffffffffu, l0, 2);
    l1 += __shfl_xor_sync(0xffffffffu, l1, 1);
    l1 += __shfl_xor_sync(0xffffffffu, l1, 2);
    float i0 = 1.0f / l0, i1 = 1.0f / l1;
    int nb = nh / NH_, hh = nh % NH_;
    int r0g = q0 + w * 16 + rq;
    size_t base0 = (((size_t)(nb * S_ + r0g)) * C_ + hh * 64 + kq * 2) * 2;
    size_t base1 = base0 + (size_t)8 * C_ * 2;
    #pragma unroll
    for (int n = 0; n < 8; n++) {
        float a0 = o[n][0] * i0, a1 = o[n][1] * i0;
        float b0 = o[n][2] * i1, b1 = o[n][3] * i1;
        float ah0 = tf32_rna(a0), ah1 = tf32_rna(a1);
        float bh0 = tf32_rna(b0), bh1 = tf32_rna(b1);
        *(float4*)(g_ao_hl + base0 + n * 16) =
            make_float4(ah0, tf32_rna(a0 - ah0), ah1, tf32_rna(a1 - ah1));
        *(float4*)(g_ao_hl + base1 + n * 16) =
            make_float4(bh0, tf32_rna(b0 - bh0), bh1, tf32_rna(b1 - bh1));
    }
}

// ---------------- launch ----------------
extern "C" void kernel_launch(void* const* d_in, const int* in_sizes, int n_in,
                              void* d_out, int out_size) {
    const float* x     = (const float*)d_in[0];
    const float* w_qkv = (const float*)d_in[1];
    const float* w_out = (const float*)d_in[2];
    const float* b_out = (const float*)d_in[3];
    float* out = (float*)d_out;

    cudaFuncSetAttribute(mma_gemm, cudaFuncAttributeMaxDynamicSharedMemorySize, GEMM_SMEM);
    cudaFuncSetAttribute(attn_mma, cudaFuncAttributeMaxDynamicSharedMemorySize, ATT2_SMEM);

    transpose_x<<<dim3(S_ / 32, C_ / 32, N_), dim3(32, 8)>>>(x);
    split_wqkv<<<(C3_ * C_ + 255) / 256, 256>>>(w_qkv);
    split_wout<<<(C_ * C_ + 255) / 256, 256>>>(w_out);

    mma_gemm<<<dim3(C3_ / 128, M_ / 128), 256, GEMM_SMEM>>>(0, nullptr, nullptr);

    attn_mma<<<dim3(S_ / 128, N_ * NH_), 256, ATT2_SMEM>>>();

    mma_gemm<<<dim3(M_ / 128, C_ / 128), 256, GEMM_SMEM>>>(1, b_out, out);
}

// round 10
// speedup vs baseline: 1.0198x; 1.0198x over previous
#include <cuda_runtime.h>
#include <cstdint>

#define N_   16
#define C_   384
#define S_   1024
#define NH_  6
#define D_   64
#define C3_  1152
#define M_   (N_*S_)

__device__ float g_tok_hi[M_*C_],  g_tok_lo[M_*C_];
__device__ float g_wqkv_hi[C3_*C_], g_wqkv_lo[C3_*C_];
__device__ float g_wout_hi[C_*C_],  g_wout_lo[C_*C_];
__device__ float g_q[N_*NH_*S_*D_];                   // fp32, 0.125 folded
__device__ float g_kh[N_*NH_*S_*D_], g_kl[N_*NH_*S_*D_];
__device__ float g_vh[N_*NH_*D_*S_], g_vl[N_*NH_*D_*S_];   // V^T
__device__ float g_ao[M_*C_];
__device__ float g_ao_hi[M_*C_], g_ao_lo[M_*C_];

__device__ __forceinline__ float tf32_rna(float x) {
    uint32_t r; asm("cvt.rna.tf32.f32 %0, %1;" : "=r"(r) : "f"(x));
    return __uint_as_float(r);
}
__device__ __forceinline__ uint32_t smem_u32(const void* p) {
    uint32_t a;
    asm("{ .reg .u64 t; cvta.to.shared.u64 t, %1; cvt.u32.u64 %0, t; }" : "=r"(a) : "l"(p));
    return a;
}
__device__ __forceinline__ uint32_t lds32(uint32_t a) {
    uint32_t v; asm volatile("ld.shared.b32 %0, [%1];" : "=r"(v) : "r"(a)); return v;
}
__device__ __forceinline__ void cp16(uint32_t saddr, const float* g) {
    size_t ga = __cvta_generic_to_global((const void*)g);
    asm volatile("cp.async.cg.shared.global [%0], [%1], 16;" :: "r"(saddr), "l"(ga) : "memory");
}
#define CP_COMMIT() asm volatile("cp.async.commit_group;" ::: "memory")
#define CP_WAIT0()  asm volatile("cp.async.wait_group 0;" ::: "memory")
#define CP_WAIT1()  asm volatile("cp.async.wait_group 1;" ::: "memory")
#define CP_WAIT2()  asm volatile("cp.async.wait_group 2;" ::: "memory")
#define FU(x) __float_as_uint(x)

#define MMA_TF32(d, a, b0, b1)                                              \
    asm volatile("mma.sync.aligned.m16n8k8.row.col.f32.tf32.tf32.f32 "      \
        "{%0,%1,%2,%3}, {%4,%5,%6,%7}, {%8,%9}, {%0,%1,%2,%3};"             \
        : "+f"((d)[0]), "+f"((d)[1]), "+f"((d)[2]), "+f"((d)[3])            \
        : "r"((a)[0]), "r"((a)[1]), "r"((a)[2]), "r"((a)[3]),               \
          "r"(b0), "r"(b1))

// ---------------- input prep ----------------
__global__ void transpose_x(const float* __restrict__ x) {
    __shared__ float t[32][33];
    int n = blockIdx.z, k0 = blockIdx.y * 32, s0 = blockIdx.x * 32;
    int tx = threadIdx.x, ty = threadIdx.y;
    const float* src = x + ((size_t)n * C_ + k0) * S_ + s0;
    #pragma unroll
    for (int j = 0; j < 4; j++)
        t[ty + 8 * j][tx] = src[(size_t)(ty + 8 * j) * S_ + tx];
    __syncthreads();
    size_t base = ((size_t)n * S_ + s0) * C_ + k0;
    #pragma unroll
    for (int j = 0; j < 4; j++) {
        float a = t[tx][ty + 8 * j];
        float h = tf32_rna(a);
        size_t o = base + (size_t)(ty + 8 * j) * C_ + tx;
        g_tok_hi[o] = h;
        g_tok_lo[o] = tf32_rna(a - h);
    }
}
__global__ void split_wqkv(const float* __restrict__ w) {
    int i = blockIdx.x * 256 + threadIdx.x;
    if (i < C3_ * C_) { float a = w[i], h = tf32_rna(a); g_wqkv_hi[i] = h; g_wqkv_lo[i] = tf32_rna(a - h); }
}
__global__ void split_wout(const float* __restrict__ w) {
    int i = blockIdx.x * 256 + threadIdx.x;
    if (i < C_ * C_) { float a = w[i], h = tf32_rna(a); g_wout_hi[i] = h; g_wout_lo[i] = tf32_rna(a - h); }
}
__global__ void split_ao() {
    int i = blockIdx.x * 256 + threadIdx.x;
    float4 a = *((const float4*)g_ao + i);
    float4 h, l;
    h.x = tf32_rna(a.x); l.x = tf32_rna(a.x - h.x);
    h.y = tf32_rna(a.y); l.y = tf32_rna(a.y - h.y);
    h.z = tf32_rna(a.z); l.z = tf32_rna(a.z - h.z);
    h.w = tf32_rna(a.w); l.w = tf32_rna(a.w - h.w);
    *((float4*)g_ao_hi + i) = h;
    *((float4*)g_ao_lo + i) = l;
}

// ---------------- 3xTF32 mma.sync GEMM, 3-stage pipeline ----------------
#define KCH 16
#define HALF_B (128*20*4)
#define STAGE_B (4*HALF_B)        // 40960
#define GEMM_SMEM (3*STAGE_B)     // 122880 -> 1 CTA/SM

__global__ __launch_bounds__(256) void mma_gemm(
    int mode, const float* __restrict__ bias, float* __restrict__ out)
{
    extern __shared__ __align__(16) char smem[];
    uint32_t sbase = smem_u32(smem);
    int tid = threadIdx.x;
    int lane = tid & 31, w = tid >> 5;
    int wm = w & 3, wn = w >> 2;
    int by = blockIdx.y, bx = blockIdx.x;

    const float *Ahp, *Alp, *Bhp, *Blp;
    if (mode == 0) { Ahp = g_tok_hi;  Alp = g_tok_lo;  Bhp = g_wqkv_hi; Blp = g_wqkv_lo; }
    else           { Ahp = g_wout_hi; Alp = g_wout_lo; Bhp = g_ao_hi;   Blp = g_ao_lo; }
    const float* Ah = Ahp + (size_t)by * 128 * C_;
    const float* Al = Alp + (size_t)by * 128 * C_;
    const float* Bh = Bhp + (size_t)bx * 128 * C_;
    const float* Bl = Blp + (size_t)bx * 128 * C_;

    float acc[2][8][4];
    #pragma unroll
    for (int i = 0; i < 2; i++)
        #pragma unroll
        for (int j = 0; j < 8; j++)
            #pragma unroll
            for (int q = 0; q < 4; q++) acc[i][j][q] = 0.0f;

    auto issue = [&](int c, int st) {
        uint32_t s0 = sbase + st * STAGE_B;
        #pragma unroll
        for (int i = 0; i < 2; i++) {
            int idx = i * 256 + tid;
            int row = idx >> 2, seg = idx & 3;
            size_t go = (size_t)row * C_ + c * KCH + seg * 4;
            uint32_t so = row * 80 + seg * 16;
            cp16(s0 + so,              Ah + go);
            cp16(s0 + HALF_B + so,     Al + go);
            cp16(s0 + 2 * HALF_B + so, Bh + go);
            cp16(s0 + 3 * HALF_B + so, Bl + go);
        }
        CP_COMMIT();
    };

    const int NCH = C_ / KCH;   // 24
    issue(0, 0);
    issue(1, 1);

    for (int c = 0; c < NCH; c++) {
        // wait for chunk c (allow the one younger in-flight group)
        if (c + 1 < NCH) { CP_WAIT1(); } else { CP_WAIT0(); }
        __syncthreads();                    // publish stage c; all reads of stage c-1 done
        if (c + 2 < NCH) issue(c + 2, (c + 2) % 3);   // overwrites stage (c-1)%3 — safe

        int st = c % 3;
        uint32_t sA  = sbase + st * STAGE_B;
        uint32_t sAl = sA + HALF_B;
        uint32_t sB  = sA + 2 * HALF_B;
        uint32_t sBl = sA + 3 * HALF_B;

        #pragma unroll
        for (int sub = 0; sub < 2; sub++) {
            int kb = sub * 8 + (lane & 3);
            uint32_t ahi[2][4], alo[2][4];
            #pragma unroll
            for (int mi = 0; mi < 2; mi++) {
                int r0 = wm * 32 + mi * 16 + (lane >> 2);
                uint32_t o0 = (uint32_t)r0 * 80 + (uint32_t)kb * 4;
                uint32_t o1 = o0 + 8 * 80;
                ahi[mi][0] = lds32(sA + o0);  ahi[mi][1] = lds32(sA + o1);
                ahi[mi][2] = lds32(sA + o0 + 16); ahi[mi][3] = lds32(sA + o1 + 16);
                alo[mi][0] = lds32(sAl + o0); alo[mi][1] = lds32(sAl + o1);
                alo[mi][2] = lds32(sAl + o0 + 16); alo[mi][3] = lds32(sAl + o1 + 16);
            }
            #pragma unroll
            for (int ni = 0; ni < 8; ni++) {
                int n0 = wn * 64 + ni * 8 + (lane >> 2);
                uint32_t bo = (uint32_t)n0 * 80 + (uint32_t)kb * 4;
                uint32_t bh0 = lds32(sB + bo),  bh1 = lds32(sB + bo + 16);
                uint32_t bl0 = lds32(sBl + bo), bl1 = lds32(sBl + bo + 16);
                #pragma unroll
                for (int mi = 0; mi < 2; mi++) {
                    MMA_TF32(acc[mi][ni], ahi[mi], bh0, bh1);
                    MMA_TF32(acc[mi][ni], ahi[mi], bl0, bl1);
                    MMA_TF32(acc[mi][ni], alo[mi], bh0, bh1);
                }
            }
        }
    }

    int row = lane >> 2, colp = (lane & 3) * 2;
    if (mode == 0) {
        #pragma unroll
        for (int ni = 0; ni < 8; ni++) {
            int rf = bx * 128 + wn * 64 + ni * 8 + colp;
            int t = rf / C_;
            int rem = rf - t * C_;
            int h = rem >> 6, d = rem & 63;
            #pragma unroll
            for (int mi = 0; mi < 2; mi++) {
                int mb = by * 128 + wm * 32 + mi * 16 + row;
                #pragma unroll
                for (int rr = 0; rr < 2; rr++) {
                    int m = mb + rr * 8;
                    int n = m >> 10, s = m & 1023;
                    int nh = n * NH_ + h;
                    float v0 = acc[mi][ni][rr * 2], v1 = acc[mi][ni][rr * 2 + 1];
                    if (t == 0) {
                        *(float2*)(g_q + ((size_t)nh * S_ + s) * D_ + d) =
                            make_float2(v0 * 0.125f, v1 * 0.125f);
                    } else if (t == 1) {
                        float h0 = tf32_rna(v0), h1 = tf32_rna(v1);
                        size_t off = ((size_t)nh * S_ + s) * D_ + d;
                        *(float2*)(g_kh + off) = make_float2(h0, h1);
                        *(float2*)(g_kl + off) = make_float2(tf32_rna(v0 - h0), tf32_rna(v1 - h1));
                    } else {
                        float h0 = tf32_rna(v0), h1 = tf32_rna(v1);
                        size_t o0 = ((size_t)nh * D_ + d) * S_ + s;
                        g_vh[o0] = h0;      g_vl[o0] = tf32_rna(v0 - h0);
                        g_vh[o0 + S_] = h1; g_vl[o0 + S_] = tf32_rna(v1 - h1);
                    }
                }
            }
        }
    } else {
        #pragma unroll
        for (int ni = 0; ni < 8; ni++) {
            int m = bx * 128 + wn * 64 + ni * 8 + colp;
            int n = m >> 10, s = m & 1023;
            #pragma unroll
            for (int mi = 0; mi < 2; mi++) {
                int cb = by * 128 + wm * 32 + mi * 16 + row;
                #pragma unroll
                for (int rr = 0; rr < 2; rr++) {
                    int cc = cb + rr * 8;
                    float bb = bias[cc];
                    float2 v = make_float2(acc[mi][ni][rr * 2] + bb,
                                           acc[mi][ni][rr * 2 + 1] + bb);
                    *(float2*)(out + ((size_t)n * C_ + cc) * S_ + s) = v;
                }
            }
        }
    }
}

// ---------------- tensor-core flash attention (round-8, unchanged) ----------
#define AST 68
#define ATT2_SMEM (43520*4)

__global__ __launch_bounds__(256) void attn_mma() {
    extern __shared__ __align__(16) float sm[];
    float* Pb  = sm;           // [128][68] (Q staging, then P)
    float* KhS = sm + 8704;    // 2 x [64][68]
    float* KlS = sm + 17408;
    float* VhS = sm + 26112;   // V^T: [d][key]
    float* VlS = sm + 34816;

    int tid = threadIdx.x;
    int lane = tid & 31, w = tid >> 5;
    int rq = lane >> 2, kq = lane & 3;
    int nh = blockIdx.y, q0 = blockIdx.x * 128;

    const float* qg  = g_q  + ((size_t)nh * S_ + q0) * D_;
    const float* khg = g_kh + (size_t)nh * S_ * D_;
    const float* klg = g_kl + (size_t)nh * S_ * D_;
    const float* vhg = g_vh + (size_t)nh * D_ * S_;
    const float* vlg = g_vl + (size_t)nh * D_ * S_;

    #pragma unroll
    for (int i = 0; i < 8; i++) {
        int idx = i * 256 + tid;
        int r = idx >> 4, sg = idx & 15;
        cp16(smem_u32(&Pb[r * AST + sg * 4]), qg + (size_t)r * D_ + sg * 4);
    }
    CP_COMMIT();

    #pragma unroll
    for (int t = 0; t < 2; t++) {
        #pragma unroll
        for (int i = 0; i < 4; i++) {
            int idx = i * 256 + tid;
            int row = idx >> 4, sg = idx & 15;
            uint32_t bo = (uint32_t)(t * 4352 + row * AST + sg * 4) * 4;
            cp16(smem_u32(KhS) + bo, khg + (size_t)(t * 64 + row) * D_ + sg * 4);
            cp16(smem_u32(KlS) + bo, klg + (size_t)(t * 64 + row) * D_ + sg * 4);
            cp16(smem_u32(VhS) + bo, vhg + (size_t)row * S_ + t * 64 + sg * 4);
            cp16(smem_u32(VlS) + bo, vlg + (size_t)row * S_ + t * 64 + sg * 4);
        }
        CP_COMMIT();
    }

    CP_WAIT2();
    __syncthreads();

    uint32_t qah[8][4], qal[8][4];
    {
        const float* q0p = &Pb[(w * 16 + rq) * AST + kq];
        #pragma unroll
        for (int s = 0; s < 8; s++) {
            float f[4];
            f[0] = q0p[s * 8];           f[1] = q0p[8 * AST + s * 8];
            f[2] = q0p[s * 8 + 4];       f[3] = q0p[8 * AST + s * 8 + 4];
            #pragma unroll
            for (int j = 0; j < 4; j++) {
                float h = tf32_rna(f[j]);
                qah[s][j] = FU(h);
                qal[s][j] = FU(tf32_rna(f[j] - h));
            }
        }
    }
    __syncthreads();

    float o[8][4];
    #pragma unroll
    for (int n = 0; n < 8; n++)
        #pragma unroll
        for (int j = 0; j < 4; j++) o[n][j] = 0.0f;
    float m0 = -1e30f, m1 = -1e30f, l0 = 0.0f, l1 = 0.0f;

    for (int kt = 0; kt < 16; kt++) {
        if (kt < 15) { CP_WAIT1(); } else { CP_WAIT0(); }
        __syncthreads();
        int boff = (kt & 1) * 4352;

        float acc[8][4];
        #pragma unroll
        for (int n = 0; n < 8; n++)
            #pragma unroll
            for (int j = 0; j < 4; j++) acc[n][j] = 0.0f;

        #pragma unroll
        for (int s = 0; s < 8; s++) {
            #pragma unroll
            for (int n = 0; n < 8; n++) {
                int bi = boff + (n * 8 + rq) * AST + s * 8 + kq;
                uint32_t bh0 = FU(KhS[bi]), bh1 = FU(KhS[bi + 4]);
                uint32_t bl0 = FU(KlS[bi]), bl1 = FU(KlS[bi + 4]);
                MMA_TF32(acc[n], qah[s], bh0, bh1);
                MMA_TF32(acc[n], qah[s], bl0, bl1);
                MMA_TF32(acc[n], qal[s], bh0, bh1);
            }
        }

        float t0 = -1e30f, t1 = -1e30f;
        #pragma unroll
        for (int n = 0; n < 8; n++) {
            t0 = fmaxf(t0, fmaxf(acc[n][0], acc[n][1]));
            t1 = fmaxf(t1, fmaxf(acc[n][2], acc[n][3]));
        }
        t0 = fmaxf(t0, __shfl_xor_sync(0xffffffffu, t0, 1));
        t0 = fmaxf(t0, __shfl_xor_sync(0xffffffffu, t0, 2));
        t1 = fmaxf(t1, __shfl_xor_sync(0xffffffffu, t1, 1));
        t1 = fmaxf(t1, __shfl_xor_sync(0xffffffffu, t1, 2));
        float mn0 = fmaxf(m0, t0), mn1 = fmaxf(m1, t1);
        float c0 = __expf(m0 - mn0), c1 = __expf(m1 - mn1);
        m0 = mn0; m1 = mn1;
        l0 *= c0; l1 *= c1;
        #pragma unroll
        for (int n = 0; n < 8; n++) {
            o[n][0] *= c0; o[n][1] *= c0; o[n][2] *= c1; o[n][3] *= c1;
        }

        float* pr = &Pb[(w * 16 + rq) * AST + kq * 2];
        #pragma unroll
        for (int n = 0; n < 8; n++) {
            float p0 = __expf(acc[n][0] - m0), p1 = __expf(acc[n][1] - m0);
            float p2 = __expf(acc[n][2] - m1), p3 = __expf(acc[n][3] - m1);
            l0 += p0 + p1; l1 += p2 + p3;
            *(float2*)(pr + n * 8)           = make_float2(p0, p1);
            *(float2*)(pr + 8 * AST + n * 8) = make_float2(p2, p3);
        }
        __syncwarp();

        const float* pa = &Pb[(w * 16 + rq) * AST + kq];
        #pragma unroll
        for (int s = 0; s < 8; s++) {
            float f[4];
            f[0] = pa[s * 8];       f[1] = pa[8 * AST + s * 8];
            f[2] = pa[s * 8 + 4];   f[3] = pa[8 * AST + s * 8 + 4];
            uint32_t ph[4], pl[4];
            #pragma unroll
            for (int j = 0; j < 4; j++) {
                float h = tf32_rna(f[j]);
                ph[j] = FU(h);
                pl[j] = FU(tf32_rna(f[j] - h));
            }
            #pragma unroll
            for (int n = 0; n < 8; n++) {
                int bi = boff + (n * 8 + rq) * AST + s * 8 + kq;
                uint32_t bh0 = FU(VhS[bi]), bh1 = FU(VhS[bi + 4]);
                uint32_t bl0 = FU(VlS[bi]), bl1 = FU(VlS[bi + 4]);
                MMA_TF32(o[n], ph, bh0, bh1);
                MMA_TF32(o[n], ph, bl0, bl1);
                MMA_TF32(o[n], pl, bh0, bh1);
            }
        }
        __syncthreads();

        if (kt + 2 < 16) {
            int t = kt + 2;
            #pragma unroll
            for (int i = 0; i < 4; i++) {
                int idx = i * 256 + tid;
                int row = idx >> 4, sg = idx & 15;
                uint32_t bo = (uint32_t)(boff + row * AST + sg * 4) * 4;
                cp16(smem_u32(KhS) + bo, khg + (size_t)(t * 64 + row) * D_ + sg * 4);
                cp16(smem_u32(KlS) + bo, klg + (size_t)(t * 64 + row) * D_ + sg * 4);
                cp16(smem_u32(VhS) + bo, vhg + (size_t)row * S_ + t * 64 + sg * 4);
                cp16(smem_u32(VlS) + bo, vlg + (size_t)row * S_ + t * 64 + sg * 4);
            }
            CP_COMMIT();
        }
    }

    l0 += __shfl_xor_sync(0xffffffffu, l0, 1);
    l0 += __shfl_xor_sync(0xffffffffu, l0, 2);
    l1 += __shfl_xor_sync(0xffffffffu, l1, 1);
    l1 += __shfl_xor_sync(0xffffffffu, l1, 2);
    float i0 = 1.0f / l0, i1 = 1.0f / l1;
    int nb = nh / NH_, h = nh % NH_;
    int r0g = q0 + w * 16 + rq;
    float* d0 = g_ao + ((size_t)(nb * S_ + r0g)) * C_ + h * 64 + kq * 2;
    float* d1 = d0 + 8 * C_;
    #pragma unroll
    for (int n = 0; n < 8; n++) {
        *(float2*)(d0 + n * 8) = make_float2(o[n][0] * i0, o[n][1] * i0);
        *(float2*)(d1 + n * 8) = make_float2(o[n][2] * i1, o[n][3] * i1);
    }
}

// ---------------- launch ----------------
extern "C" void kernel_launch(void* const* d_in, const int* in_sizes, int n_in,
                              void* d_out, int out_size) {
    const float* x     = (const float*)d_in[0];
    const float* w_qkv = (const float*)d_in[1];
    const float* w_out = (const float*)d_in[2];
    const float* b_out = (const float*)d_in[3];
    float* out = (float*)d_out;

    cudaFuncSetAttribute(mma_gemm, cudaFuncAttributeMaxDynamicSharedMemorySize, GEMM_SMEM);
    cudaFuncSetAttribute(attn_mma, cudaFuncAttributeMaxDynamicSharedMemorySize, ATT2_SMEM);

    transpose_x<<<dim3(S_ / 32, C_ / 32, N_), dim3(32, 8)>>>(x);
    split_wqkv<<<(C3_ * C_ + 255) / 256, 256>>>(w_qkv);
    split_wout<<<(C_ * C_ + 255) / 256, 256>>>(w_out);

    mma_gemm<<<dim3(C3_ / 128, M_ / 128), 256, GEMM_SMEM>>>(0, nullptr, nullptr);

    attn_mma<<<dim3(S_ / 128, N_ * NH_), 256, ATT2_SMEM>>>();

    split_ao<<<(M_ * C_ / 4) / 256, 256>>>();

    mma_gemm<<<dim3(M_ / 128, C_ / 128), 256, GEMM_SMEM>>>(1, b_out, out);
}

// round 11
// speedup vs baseline: 2.0117x; 1.9726x over previous
#include <cuda_runtime.h>
#include <cuda_bf16.h>
#include <cstdint>

#define N_   16
#define C_   384
#define S_   1024
#define NH_  6
#define D_   64
#define C3_  1152
#define M_   (N_*S_)

typedef __nv_bfloat16 bf16;

__device__ bf16 g_tok_hi[M_*C_],  g_tok_lo[M_*C_];
__device__ bf16 g_wqkv_hi[C3_*C_], g_wqkv_lo[C3_*C_];
__device__ bf16 g_wout_hi[C_*C_],  g_wout_lo[C_*C_];
__device__ float g_q[N_*NH_*S_*D_];                    // fp32, 0.125 folded
__device__ bf16 g_kh[N_*NH_*S_*D_], g_kl[N_*NH_*S_*D_];
__device__ bf16 g_vh[N_*NH_*D_*S_], g_vl[N_*NH_*D_*S_];   // V^T [nh][d][s]
__device__ bf16 g_ao_hi[M_*C_], g_ao_lo[M_*C_];

__device__ __forceinline__ uint32_t smem_u32(const void* p) {
    uint32_t a;
    asm("{ .reg .u64 t; cvta.to.shared.u64 t, %1; cvt.u32.u64 %0, t; }" : "=r"(a) : "l"(p));
    return a;
}
__device__ __forceinline__ uint32_t lds32(uint32_t a) {
    uint32_t v; asm volatile("ld.shared.b32 %0, [%1];" : "=r"(v) : "r"(a)); return v;
}
__device__ __forceinline__ void cp16(uint32_t saddr, const void* g) {
    size_t ga = __cvta_generic_to_global(g);
    asm volatile("cp.async.cg.shared.global [%0], [%1], 16;" :: "r"(saddr), "l"(ga) : "memory");
}
#define CP_COMMIT() asm volatile("cp.async.commit_group;" ::: "memory")
#define CP_WAIT0()  asm volatile("cp.async.wait_group 0;" ::: "memory")
#define CP_WAIT1()  asm volatile("cp.async.wait_group 1;" ::: "memory")
#define CP_WAIT2()  asm volatile("cp.async.wait_group 2;" ::: "memory")

// pack two floats' bf16 roundings into one .b32 (lo half = first elem)
__device__ __forceinline__ uint32_t bfpair(float a, float b) {
    __nv_bfloat162 t; t.x = __float2bfloat16(a); t.y = __float2bfloat16(b);
    return *(uint32_t*)&t;
}
// split two floats into bf16 hi-pair + bf16 lo-pair
__device__ __forceinline__ void bfsplit2(float a, float b, uint32_t& h, uint32_t& l) {
    bf16 ha = __float2bfloat16(a), hb = __float2bfloat16(b);
    __nv_bfloat162 hp; hp.x = ha; hp.y = hb;
    h = *(uint32_t*)&hp;
    l = bfpair(a - __bfloat162float(ha), b - __bfloat162float(hb));
}

#define MMA_BF16(d, a, b0, b1)                                                \
    asm volatile("mma.sync.aligned.m16n8k16.row.col.f32.bf16.bf16.f32 "       \
        "{%0,%1,%2,%3}, {%4,%5,%6,%7}, {%8,%9}, {%0,%1,%2,%3};"               \
        : "+f"((d)[0]), "+f"((d)[1]), "+f"((d)[2]), "+f"((d)[3])              \
        : "r"((a)[0]), "r"((a)[1]), "r"((a)[2]), "r"((a)[3]),                 \
          "r"(b0), "r"(b1))

// ---------------- input prep ----------------
__global__ void transpose_x(const float* __restrict__ x) {
    __shared__ float t[32][33];
    int n = blockIdx.z, k0 = blockIdx.y * 32, s0 = blockIdx.x * 32;
    int tx = threadIdx.x, ty = threadIdx.y;
    const float* src = x + ((size_t)n * C_ + k0) * S_ + s0;
    #pragma unroll
    for (int j = 0; j < 4; j++)
        t[ty + 8 * j][tx] = src[(size_t)(ty + 8 * j) * S_ + tx];
    __syncthreads();
    size_t base = ((size_t)n * S_ + s0) * C_ + k0;
    #pragma unroll
    for (int j = 0; j < 4; j++) {
        float a = t[tx][ty + 8 * j];
        bf16 h = __float2bfloat16(a);
        size_t o = base + (size_t)(ty + 8 * j) * C_ + tx;
        g_tok_hi[o] = h;
        g_tok_lo[o] = __float2bfloat16(a - __bfloat162float(h));
    }
}
__global__ void split_wqkv(const float* __restrict__ w) {
    int i = blockIdx.x * 256 + threadIdx.x;
    if (i < C3_ * C_) {
        float a = w[i]; bf16 h = __float2bfloat16(a);
        g_wqkv_hi[i] = h; g_wqkv_lo[i] = __float2bfloat16(a - __bfloat162float(h));
    }
}
__global__ void split_wout(const float* __restrict__ w) {
    int i = blockIdx.x * 256 + threadIdx.x;
    if (i < C_ * C_) {
        float a = w[i]; bf16 h = __float2bfloat16(a);
        g_wout_hi[i] = h; g_wout_lo[i] = __float2bfloat16(a - __bfloat162float(h));
    }
}

// ---------------- 3xBF16 mma.sync GEMM (2-stage, KCH=32) ----------------
// smem row: 32 bf16 = 64B, padded to 80B (bank pattern 20r+kq: conflict-free)
#define KCH 32
#define HALF_B (128*80)            // 10240 B per array
#define STAGE_B (4*HALF_B)         // 40960
#define GEMM_SMEM (2*STAGE_B)      // 81920 -> 2 CTA/SM

__global__ __launch_bounds__(256) void mma_gemm(
    int mode, const float* __restrict__ bias, float* __restrict__ out)
{
    extern __shared__ __align__(16) char smem[];
    uint32_t sbase = smem_u32(smem);
    int tid = threadIdx.x;
    int lane = tid & 31, w = tid >> 5;
    int wm = w & 3, wn = w >> 2;
    int by = blockIdx.y, bx = blockIdx.x;
    int rq = lane >> 2, kq = lane & 3;

    const bf16 *Ahp, *Alp, *Bhp, *Blp;
    if (mode == 0) { Ahp = g_tok_hi;  Alp = g_tok_lo;  Bhp = g_wqkv_hi; Blp = g_wqkv_lo; }
    else           { Ahp = g_wout_hi; Alp = g_wout_lo; Bhp = g_ao_hi;   Blp = g_ao_lo; }
    const bf16* Ah = Ahp + (size_t)by * 128 * C_;
    const bf16* Al = Alp + (size_t)by * 128 * C_;
    const bf16* Bh = Bhp + (size_t)bx * 128 * C_;
    const bf16* Bl = Blp + (size_t)bx * 128 * C_;

    float acc[2][8][4];
    #pragma unroll
    for (int i = 0; i < 2; i++)
        #pragma unroll
        for (int j = 0; j < 8; j++)
            #pragma unroll
            for (int q = 0; q < 4; q++) acc[i][j][q] = 0.0f;

    auto issue = [&](int c, int st) {
        uint32_t s0 = sbase + st * STAGE_B;
        #pragma unroll
        for (int i = 0; i < 2; i++) {
            int idx = i * 256 + tid;            // 0..511
            int row = idx >> 2, seg = idx & 3;  // 4 segs x 8 bf16 = 32 elems/row
            size_t go = (size_t)row * C_ + c * KCH + seg * 8;
            uint32_t so = row * 80 + seg * 16;
            cp16(s0 + so,              Ah + go);
            cp16(s0 + HALF_B + so,     Al + go);
            cp16(s0 + 2 * HALF_B + so, Bh + go);
            cp16(s0 + 3 * HALF_B + so, Bl + go);
        }
        CP_COMMIT();
    };

    const int NCH = C_ / KCH;   // 12
    issue(0, 0);
    for (int c = 0; c < NCH; c++) {
        int st = c & 1;
        if (c + 1 < NCH) { issue(c + 1, st ^ 1); CP_WAIT1(); }
        else             { CP_WAIT0(); }
        __syncthreads();

        uint32_t sA  = sbase + st * STAGE_B;
        uint32_t sAl = sA + HALF_B;
        uint32_t sB  = sA + 2 * HALF_B;
        uint32_t sBl = sA + 3 * HALF_B;

        #pragma unroll
        for (int sub = 0; sub < 2; sub++) {     // two k16 halves of the k32 chunk
            uint32_t ko = (uint32_t)(sub * 32 + kq * 4);
            uint32_t ahi[2][4], alo[2][4];
            #pragma unroll
            for (int mi = 0; mi < 2; mi++) {
                uint32_t o0 = (uint32_t)(wm * 32 + mi * 16 + rq) * 80 + ko;
                ahi[mi][0] = lds32(sA + o0);       ahi[mi][1] = lds32(sA + o0 + 640);
                ahi[mi][2] = lds32(sA + o0 + 16);  ahi[mi][3] = lds32(sA + o0 + 656);
                alo[mi][0] = lds32(sAl + o0);      alo[mi][1] = lds32(sAl + o0 + 640);
                alo[mi][2] = lds32(sAl + o0 + 16); alo[mi][3] = lds32(sAl + o0 + 656);
            }
            #pragma unroll
            for (int ni = 0; ni < 8; ni++) {
                uint32_t bo = (uint32_t)(wn * 64 + ni * 8 + rq) * 80 + ko;
                uint32_t bh0 = lds32(sB + bo),  bh1 = lds32(sB + bo + 16);
                uint32_t bl0 = lds32(sBl + bo), bl1 = lds32(sBl + bo + 16);
                #pragma unroll
                for (int mi = 0; mi < 2; mi++) {
                    MMA_BF16(acc[mi][ni], ahi[mi], bh0, bh1);
                    MMA_BF16(acc[mi][ni], ahi[mi], bl0, bl1);
                    MMA_BF16(acc[mi][ni], alo[mi], bh0, bh1);
                }
            }
        }
        __syncthreads();
    }

    int colp = kq * 2;
    if (mode == 0) {
        #pragma unroll
        for (int ni = 0; ni < 8; ni++) {
            int rf = bx * 128 + wn * 64 + ni * 8 + colp;
            int t = rf / C_;
            int rem = rf - t * C_;
            int h = rem >> 6, d = rem & 63;
            #pragma unroll
            for (int mi = 0; mi < 2; mi++) {
                int mb = by * 128 + wm * 32 + mi * 16 + rq;
                #pragma unroll
                for (int rr = 0; rr < 2; rr++) {
                    int m = mb + rr * 8;
                    int n = m >> 10, s = m & 1023;
                    int nh = n * NH_ + h;
                    float v0 = acc[mi][ni][rr * 2], v1 = acc[mi][ni][rr * 2 + 1];
                    if (t == 0) {
                        *(float2*)(g_q + ((size_t)nh * S_ + s) * D_ + d) =
                            make_float2(v0 * 0.125f, v1 * 0.125f);
                    } else if (t == 1) {
                        float h0 = __bfloat162float(__float2bfloat16(v0));
                        float h1 = __bfloat162float(__float2bfloat16(v1));
                        size_t off = ((size_t)nh * S_ + s) * D_ + d;
                        *(uint32_t*)(g_kh + off) = bfpair(v0, v1);
                        *(uint32_t*)(g_kl + off) = bfpair(v0 - h0, v1 - h1);
                    } else {
                        float h0 = __bfloat162float(__float2bfloat16(v0));
                        float h1 = __bfloat162float(__float2bfloat16(v1));
                        size_t o0 = ((size_t)nh * D_ + d) * S_ + s;
                        g_vh[o0] = __float2bfloat16(v0);
                        g_vl[o0] = __float2bfloat16(v0 - h0);
                        g_vh[o0 + S_] = __float2bfloat16(v1);
                        g_vl[o0 + S_] = __float2bfloat16(v1 - h1);
                    }
                }
            }
        }
    } else {
        #pragma unroll
        for (int ni = 0; ni < 8; ni++) {
            int m = bx * 128 + wn * 64 + ni * 8 + colp;
            int n = m >> 10, s = m & 1023;
            #pragma unroll
            for (int mi = 0; mi < 2; mi++) {
                int cb = by * 128 + wm * 32 + mi * 16 + rq;
                #pragma unroll
                for (int rr = 0; rr < 2; rr++) {
                    int cc = cb + rr * 8;
                    float bb = bias[cc];
                    float2 v = make_float2(acc[mi][ni][rr * 2] + bb,
                                           acc[mi][ni][rr * 2 + 1] + bb);
                    *(float2*)(out + ((size_t)n * C_ + cc) * S_ + s) = v;
                }
            }
        }
    }
}

// ---------------- bf16x3 tensor-core flash attention ----------------
// 256 thr; warp w owns q rows [w*16, w*16+16). 64-key tiles, 16 iters.
// K/V tiles bf16, row 64 elems (128B) padded to 144B (bank 36r+kq: conflict-free).
#define AST 68
#define KVROW 144
#define KVTILE (64*KVROW)          // 9216 B
#define ATT2_SMEM (34816 + 4*2*KVTILE)   // Pb fp32 + 4 arrays x 2 stages = 108544

__global__ __launch_bounds__(256) void attn_mma() {
    extern __shared__ __align__(16) char smc[];
    float* Pb = (float*)smc;                 // [128][68] fp32: Q staging, then P
    uint32_t sb  = smem_u32(smc);
    uint32_t khS = sb + 34816;
    uint32_t klS = khS + 2 * KVTILE;
    uint32_t vhS = klS + 2 * KVTILE;
    uint32_t vlS = vhS + 2 * KVTILE;

    int tid = threadIdx.x;
    int lane = tid & 31, w = tid >> 5;
    int rq = lane >> 2, kq = lane & 3;
    int nh = blockIdx.y, q0 = blockIdx.x * 128;

    const float* qg = g_q  + ((size_t)nh * S_ + q0) * D_;
    const bf16* khg = g_kh + (size_t)nh * S_ * D_;
    const bf16* klg = g_kl + (size_t)nh * S_ * D_;
    const bf16* vhg = g_vh + (size_t)nh * D_ * S_;
    const bf16* vlg = g_vl + (size_t)nh * D_ * S_;

    // group 1: Q -> Pb
    #pragma unroll
    for (int i = 0; i < 8; i++) {
        int idx = i * 256 + tid;
        int r = idx >> 4, sg = idx & 15;
        cp16(smem_u32(&Pb[r * AST + sg * 4]), qg + (size_t)r * D_ + sg * 4);
    }
    CP_COMMIT();

    // groups 2,3: K/V tiles 0,1 (each array: 64 rows x 8 segs of 16B)
    #pragma unroll
    for (int t = 0; t < 2; t++) {
        #pragma unroll
        for (int i = 0; i < 2; i++) {
            int idx = i * 256 + tid;
            int row = idx >> 3, sg = idx & 7;
            uint32_t so = (uint32_t)(t * KVTILE + row * KVROW) + sg * 16;
            cp16(khS + so, khg + (size_t)(t * 64 + row) * D_ + sg * 8);
            cp16(klS + so, klg + (size_t)(t * 64 + row) * D_ + sg * 8);
            cp16(vhS + so, vhg + (size_t)row * S_ + t * 64 + sg * 8);
            cp16(vlS + so, vlg + (size_t)row * S_ + t * 64 + sg * 8);
        }
        CP_COMMIT();
    }

    CP_WAIT2();
    __syncthreads();

    // Q fragments: 4 k16-subs over d, bf16 hi/lo split (exact within bf16x2)
    uint32_t qah[4][4], qal[4][4];
    {
        const float* qp = &Pb[(w * 16 + rq) * AST];
        #pragma unroll
        for (int s = 0; s < 4; s++) {
            int d0 = s * 16 + 2 * kq;
            bfsplit2(qp[d0],            qp[d0 + 1],            qah[s][0], qal[s][0]);
            bfsplit2(qp[8 * AST + d0],  qp[8 * AST + d0 + 1],  qah[s][1], qal[s][1]);
            bfsplit2(qp[d0 + 8],        qp[d0 + 9],            qah[s][2], qal[s][2]);
            bfsplit2(qp[8 * AST + d0 + 8], qp[8 * AST + d0 + 9], qah[s][3], qal[s][3]);
        }
    }
    __syncthreads();

    float o[8][4];
    #pragma unroll
    for (int n = 0; n < 8; n++)
        #pragma unroll
        for (int j = 0; j < 4; j++) o[n][j] = 0.0f;
    float m0 = -1e30f, m1 = -1e30f, l0 = 0.0f, l1 = 0.0f;

    for (int kt = 0; kt < 16; kt++) {
        if (kt < 15) { CP_WAIT1(); } else { CP_WAIT0(); }
        __syncthreads();
        uint32_t boff = (uint32_t)((kt & 1) * KVTILE);

        // ---- QK^T (3-pass bf16) ----
        float acc[8][4];
        #pragma unroll
        for (int n = 0; n < 8; n++)
            #pragma unroll
            for (int j = 0; j < 4; j++) acc[n][j] = 0.0f;

        #pragma unroll
        for (int s = 0; s < 4; s++) {
            #pragma unroll
            for (int n = 0; n < 8; n++) {
                uint32_t bo = boff + (uint32_t)(n * 8 + rq) * KVROW + s * 32 + kq * 4;
                uint32_t bh0 = lds32(khS + bo), bh1 = lds32(khS + bo + 16);
                uint32_t bl0 = lds32(klS + bo), bl1 = lds32(klS + bo + 16);
                MMA_BF16(acc[n], qah[s], bh0, bh1);
                MMA_BF16(acc[n], qah[s], bl0, bl1);
                MMA_BF16(acc[n], qal[s], bh0, bh1);
            }
        }

        // ---- softmax (rows rq, rq+8 of this warp's 16) ----
        float t0 = -1e30f, t1 = -1e30f;
        #pragma unroll
        for (int n = 0; n < 8; n++) {
            t0 = fmaxf(t0, fmaxf(acc[n][0], acc[n][1]));
            t1 = fmaxf(t1, fmaxf(acc[n][2], acc[n][3]));
        }
        t0 = fmaxf(t0, __shfl_xor_sync(0xffffffffu, t0, 1));
        t0 = fmaxf(t0, __shfl_xor_sync(0xffffffffu, t0, 2));
        t1 = fmaxf(t1, __shfl_xor_sync(0xffffffffu, t1, 1));
        t1 = fmaxf(t1, __shfl_xor_sync(0xffffffffu, t1, 2));
        float mn0 = fmaxf(m0, t0), mn1 = fmaxf(m1, t1);
        float c0 = __expf(m0 - mn0), c1 = __expf(m1 - mn1);
        m0 = mn0; m1 = mn1;
        l0 *= c0; l1 *= c1;
        #pragma unroll
        for (int n = 0; n < 8; n++) {
            o[n][0] *= c0; o[n][1] *= c0; o[n][2] *= c1; o[n][3] *= c1;
        }

        float* pr = &Pb[(w * 16 + rq) * AST + kq * 2];
        #pragma unroll
        for (int n = 0; n < 8; n++) {
            float p0 = __expf(acc[n][0] - m0), p1 = __expf(acc[n][1] - m0);
            float p2 = __expf(acc[n][2] - m1), p3 = __expf(acc[n][3] - m1);
            l0 += p0 + p1; l1 += p2 + p3;
            *(float2*)(pr + n * 8)           = make_float2(p0, p1);
            *(float2*)(pr + 8 * AST + n * 8) = make_float2(p2, p3);
        }
        __syncwarp();

        // ---- PV (3-pass bf16; P split in registers) ----
        const float* pa = &Pb[(w * 16 + rq) * AST];
        #pragma unroll
        for (int t4 = 0; t4 < 4; t4++) {
            int k0 = t4 * 16 + 2 * kq;
            uint32_t ph[4], pl[4];
            bfsplit2(pa[k0],           pa[k0 + 1],           ph[0], pl[0]);
            bfsplit2(pa[8 * AST + k0], pa[8 * AST + k0 + 1], ph[1], pl[1]);
            bfsplit2(pa[k0 + 8],       pa[k0 + 9],           ph[2], pl[2]);
            bfsplit2(pa[8 * AST + k0 + 8], pa[8 * AST + k0 + 9], ph[3], pl[3]);
            #pragma unroll
            for (int n = 0; n < 8; n++) {
                uint32_t bo = boff + (uint32_t)(n * 8 + rq) * KVROW + t4 * 32 + kq * 4;
                uint32_t bh0 = lds32(vhS + bo), bh1 = lds32(vhS + bo + 16);
                uint32_t bl0 = lds32(vlS + bo), bl1 = lds32(vlS + bo + 16);
                MMA_BF16(o[n], ph, bh0, bh1);
                MMA_BF16(o[n], ph, bl0, bl1);
                MMA_BF16(o[n], pl, bh0, bh1);
            }
        }
        __syncthreads();

        if (kt + 2 < 16) {
            int t = kt + 2;
            #pragma unroll
            for (int i = 0; i < 2; i++) {
                int idx = i * 256 + tid;
                int row = idx >> 3, sg = idx & 7;
                uint32_t so = boff + (uint32_t)(row * KVROW) + sg * 16;
                cp16(khS + so, khg + (size_t)(t * 64 + row) * D_ + sg * 8);
                cp16(klS + so, klg + (size_t)(t * 64 + row) * D_ + sg * 8);
                cp16(vhS + so, vhg + (size_t)row * S_ + t * 64 + sg * 8);
                cp16(vlS + so, vlg + (size_t)row * S_ + t * 64 + sg * 8);
            }
            CP_COMMIT();
        }
    }

    // ---- epilogue: normalize + bf16 hi/lo split -> g_ao_hi/lo ----
    l0 += __shfl_xor_sync(0xffffffffu, l0, 1);
    l0 += __shfl_xor_sync(0xffffffffu, l0, 2);
    l1 += __shfl_xor_sync(0xffffffffu, l1, 1);
    l1 += __shfl_xor_sync(0xffffffffu, l1, 2);
    float i0 = 1.0f / l0, i1 = 1.0f / l1;
    int nb = nh / NH_, hh = nh % NH_;
    int r0g = q0 + w * 16 + rq;
    size_t m0r = (size_t)(nb * S_ + r0g) * C_ + hh * 64 + kq * 2;
    size_t m1r = m0r + (size_t)8 * C_;
    #pragma unroll
    for (int n = 0; n < 8; n++) {
        float a0 = o[n][0] * i0, a1 = o[n][1] * i0;
        float b0 = o[n][2] * i1, b1 = o[n][3] * i1;
        uint32_t h, l;
        bfsplit2(a0, a1, h, l);
        *(uint32_t*)(g_ao_hi + m0r + n * 8) = h;
        *(uint32_t*)(g_ao_lo + m0r + n * 8) = l;
        bfsplit2(b0, b1, h, l);
        *(uint32_t*)(g_ao_hi + m1r + n * 8) = h;
        *(uint32_t*)(g_ao_lo + m1r + n * 8) = l;
    }
}

// ---------------- launch ----------------
extern "C" void kernel_launch(void* const* d_in, const int* in_sizes, int n_in,
                              void* d_out, int out_size) {
    const float* x     = (const float*)d_in[0];
    const float* w_qkv = (const float*)d_in[1];
    const float* w_out = (const float*)d_in[2];
    const float* b_out = (const float*)d_in[3];
    float* out = (float*)d_out;

    cudaFuncSetAttribute(mma_gemm, cudaFuncAttributeMaxDynamicSharedMemorySize, GEMM_SMEM);
    cudaFuncSetAttribute(attn_mma, cudaFuncAttributeMaxDynamicSharedMemorySize, ATT2_SMEM);

    transpose_x<<<dim3(S_ / 32, C_ / 32, N_), dim3(32, 8)>>>(x);
    split_wqkv<<<(C3_ * C_ + 255) / 256, 256>>>(w_qkv);
    split_wout<<<(C_ * C_ + 255) / 256, 256>>>(w_out);

    mma_gemm<<<dim3(C3_ / 128, M_ / 128), 256, GEMM_SMEM>>>(0, nullptr, nullptr);

    attn_mma<<<dim3(S_ / 128, N_ * NH_), 256, ATT2_SMEM>>>();

    mma_gemm<<<dim3(M_ / 128, C_ / 128), 256, GEMM_SMEM>>>(1, b_out, out);
}